// round 5
// baseline (speedup 1.0000x reference)
#include <cuda_runtime.h>
#include <math.h>
#include <stdint.h>

// ---------------------------------------------------------------------------
// Problem constants
// ---------------------------------------------------------------------------
namespace cfg {
constexpr int PRED = 100000, TOTAL = 120000, NUI = 200000, NODES = 220000;
constexpr float EPS = 1e-5f;

constexpr size_t S_NODE = (size_t)NODES * 64;
constexpr size_t S_NUI  = (size_t)NUI * 64;
constexpr size_t S_PRED = (size_t)PRED * 64;
constexpr size_t S_TOT  = (size_t)TOTAL * 64;

// float pool offsets
constexpr size_t O_E    = 0;
constexpr size_t O_UIE  = O_E + S_NODE;
constexpr size_t O_FS   = O_UIE + S_NUI;
constexpr size_t O_FD   = O_FS + S_NUI;
constexpr size_t O_G0   = O_FD + S_NUI;
constexpr size_t O_G1   = O_G0 + S_NUI;
constexpr size_t O_I2U  = O_G1 + S_PRED;
constexpr size_t O_SOC  = O_I2U + S_PRED;
constexpr size_t O_SIE  = O_SOC + S_PRED;
constexpr size_t O_UIM  = O_SIE + S_PRED;
constexpr size_t O_TMP  = O_UIM + S_PRED;
constexpr size_t O_HUP  = O_TMP + S_PRED;
constexpr size_t O_HUS  = O_HUP + S_PRED;
constexpr size_t O_SP   = O_HUS + S_PRED;
constexpr size_t O_USE  = O_SP + S_PRED;
constexpr size_t O_T1   = O_USE + S_PRED;
constexpr size_t O_T2   = O_T1 + S_TOT;
constexpr size_t O_H    = O_T2 + S_TOT;
constexpr size_t O_CH2  = O_H + S_TOT;
constexpr size_t O_DINV = O_CH2 + S_TOT;
constexpr size_t O_STATS= O_DINV + TOTAL;
constexpr size_t FPOOL  = O_STATS + 128;

// int pool: per-graph CSR structures
constexpr int  NG = 5;
constexpr size_t RPSZ  = 200002;
constexpr size_t I_RP  = 0;                       // 5 x RPSZ
constexpr size_t I_CNT = I_RP + NG * RPSZ;        // 5 x RPSZ
constexpr size_t I_BS  = I_CNT + NG * RPSZ;       // 5 x 512
constexpr size_t I_BS2 = I_BS + NG * 512;         // 5 x 512
constexpr size_t I_CSR = I_BS2 + NG * 512;        // 6.5M
constexpr size_t CSR_OFF[5] = {0, 1500000, 3000000, 4000000, 5000000};
constexpr size_t IPOOL = I_CSR + 6500000;
}  // namespace cfg

__device__ float g_f[cfg::FPOOL];
__device__ int   g_i[cfg::IPOOL];

// ---------------------------------------------------------------------------
// helpers
// ---------------------------------------------------------------------------
__device__ __forceinline__ float lrelu(float x, float s) { return x > 0.f ? x : s * x; }

__device__ __forceinline__ unsigned long long pk2(float x, float y) {
    unsigned long long r;
    asm("mov.b64 %0, {%1, %2};" : "=l"(r) : "f"(x), "f"(y));
    return r;
}
__device__ __forceinline__ unsigned long long ffma2(unsigned long long a,
                                                    unsigned long long b,
                                                    unsigned long long c) {
    unsigned long long d;
    asm("fma.rn.f32x2 %0, %1, %2, %3;" : "=l"(d) : "l"(a), "l"(b), "l"(c));
    return d;
}
__device__ __forceinline__ float2 upk2(unsigned long long v) {
    float2 f;
    asm("mov.b64 {%0, %1}, %2;" : "=f"(f.x), "=f"(f.y) : "l"(v));
    return f;
}

// ---------------------------------------------------------------------------
// GEMM: Y[n x 64] = act( base + X[n x 64] @ W[64 x 64] )
// flags bit0: base = bias (else accumulate into existing Y)
// flags bit1: leaky_relu(0.01)
// Block: 128 rows x 64 cols, 128 threads.
// Row-pair FFMA2: accumulator pair = (row r, row r+1) for one column.
// W pre-duplicated in smem as (w,w) 8B entries, interleaved so LDS is
// conflict-free. Inner loop per k: 6 x LDS.128 + 32 x FFMA2, no packing movs.
// Thread (tx,ty): rows ty*8..ty*8+7, cols {2tx+16j, 2tx+16j+1} j=0..3.
// ---------------------------------------------------------------------------
__global__ __launch_bounds__(128, 3) void gemm64(
    const float* __restrict__ X, const float* __restrict__ W,
    const float* __restrict__ bias, float* __restrict__ Y, int n, int flags)
{
    extern __shared__ char smem[];
    float* Xs = (float*)smem;                                   // [k][row] 64 x 132
    unsigned long long* Ws2 = (unsigned long long*)(smem + 64 * 132 * 4);  // [k][col] 64 x 66 pairs
    const int t = threadIdx.x;
    const int m0 = blockIdx.x * 128;

    // W -> duplicated pairs in smem
    {
        const float4* W4 = (const float4*)W;
#pragma unroll
        for (int i = 0; i < 8; i++) {
            int idx = i * 128 + t;          // 0..1023 float4
            int k = idx >> 4, c4 = (idx & 15) * 4;
            float4 w = W4[idx];
            ulonglong2 p0, p1;
            p0.x = pk2(w.x, w.x); p0.y = pk2(w.y, w.y);
            p1.x = pk2(w.z, w.z); p1.y = pk2(w.w, w.w);
            *(ulonglong2*)&Ws2[k * 66 + c4]     = p0;
            *(ulonglong2*)&Ws2[k * 66 + c4 + 2] = p1;
        }
    }
    // X tile transposed: [k][row], 128 rows
#pragma unroll
    for (int i = 0; i < 16; i++) {
        int idx = i * 128 + t;              // 0..2047
        int r = idx >> 4, k4 = idx & 15;
        float4 v = make_float4(0.f, 0.f, 0.f, 0.f);
        if (m0 + r < n) v = *(const float4*)&X[(size_t)(m0 + r) * 64 + k4 * 4];
        Xs[(k4 * 4 + 0) * 132 + r] = v.x;
        Xs[(k4 * 4 + 1) * 132 + r] = v.y;
        Xs[(k4 * 4 + 2) * 132 + r] = v.z;
        Xs[(k4 * 4 + 3) * 132 + r] = v.w;
    }
    __syncthreads();

    const int tx = t & 7, ty = t >> 3;      // tx: col phase, ty: 16 row groups of 8
    unsigned long long acc[4][8];           // [rowpair][colslot]
#pragma unroll
    for (int i = 0; i < 4; i++)
#pragma unroll
        for (int j = 0; j < 8; j++) acc[i][j] = 0ull;

#pragma unroll 8
    for (int k = 0; k < 64; k++) {
        ulonglong2 a01 = *(const ulonglong2*)&Xs[k * 132 + ty * 8];      // rowpairs (0,1),(2,3)
        ulonglong2 a23 = *(const ulonglong2*)&Xs[k * 132 + ty * 8 + 4];  // rowpairs (4,5),(6,7)
        ulonglong2 w0 = *(const ulonglong2*)&Ws2[k * 66 + tx * 2];       // cols 2tx, 2tx+1
        ulonglong2 w1 = *(const ulonglong2*)&Ws2[k * 66 + tx * 2 + 16];  // cols 2tx+16, +17
        ulonglong2 w2 = *(const ulonglong2*)&Ws2[k * 66 + tx * 2 + 32];
        ulonglong2 w3 = *(const ulonglong2*)&Ws2[k * 66 + tx * 2 + 48];
        unsigned long long ap[4] = {a01.x, a01.y, a23.x, a23.y};
        unsigned long long wd[8] = {w0.x, w0.y, w1.x, w1.y, w2.x, w2.y, w3.x, w3.y};
#pragma unroll
        for (int i = 0; i < 4; i++) {
#pragma unroll
            for (int j = 0; j < 8; j++)
                acc[i][j] = ffma2(ap[i], wd[j], acc[i][j]);
        }
    }

    const bool init = flags & 1, lk = flags & 2;
    float2 bb[4];
#pragma unroll
    for (int j = 0; j < 4; j++)
        bb[j] = init ? *(const float2*)&bias[tx * 2 + 16 * j] : make_float2(0.f, 0.f);

#pragma unroll
    for (int rr = 0; rr < 8; rr++) {
        int row = m0 + ty * 8 + rr;
        if (row >= n) break;
        int rp = rr >> 1, hi = rr & 1;
        float* yp = &Y[(size_t)row * 64];
#pragma unroll
        for (int j = 0; j < 4; j++) {
            float2 pa = upk2(acc[rp][2 * j]);
            float2 pb = upk2(acc[rp][2 * j + 1]);
            float2 o;
            o.x = hi ? pa.y : pa.x;
            o.y = hi ? pb.y : pb.x;
            float2 base = init ? bb[j] : *(const float2*)&yp[tx * 2 + 16 * j];
            o.x += base.x; o.y += base.y;
            if (lk) { o.x = lrelu(o.x, .01f); o.y = lrelu(o.y, .01f); }
            *(float2*)&yp[tx * 2 + 16 * j] = o;
        }
    }
}

constexpr int GEMM_SMEM = 64 * 132 * 4 + 64 * 66 * 8;  // 67584

// ---------------------------------------------------------------------------
// BatchNorm
// ---------------------------------------------------------------------------
__global__ void bn_stats(const float* __restrict__ x, float* __restrict__ stats, int n)
{
    const int col = threadIdx.x & 63, rg = threadIdx.x >> 6;  // 256 threads
    float s = 0.f, q = 0.f;
    for (int r = blockIdx.x * 4 + rg; r < n; r += gridDim.x * 4) {
        float v = x[(size_t)r * 64 + col];
        s += v; q += v * v;
    }
    __shared__ float sh[2][4][64];
    sh[0][rg][col] = s; sh[1][rg][col] = q;
    __syncthreads();
    if (rg == 0) {
        s = sh[0][0][col] + sh[0][1][col] + sh[0][2][col] + sh[0][3][col];
        q = sh[1][0][col] + sh[1][1][col] + sh[1][2][col] + sh[1][3][col];
        atomicAdd(&stats[col], s);
        atomicAdd(&stats[64 + col], q);
    }
}

__global__ void bn_apply(const float* __restrict__ x, const float* __restrict__ stats,
                         const float* __restrict__ g, const float* __restrict__ b,
                         float* __restrict__ y, int n, int leaky)
{
    size_t idx = (size_t)blockIdx.x * blockDim.x + threadIdx.x;
    size_t tot = (size_t)n * 64;
    if (idx >= tot) return;
    int col = idx & 63;
    float mu  = stats[col] / (float)n;
    float var = stats[64 + col] / (float)n - mu * mu;
    float sc = rsqrtf(var + cfg::EPS) * g[col];
    float v = (x[idx] - mu) * sc + b[col];
    y[idx] = leaky ? lrelu(v, .01f) : v;
}

// ---------------------------------------------------------------------------
// CSR build
// ---------------------------------------------------------------------------
__global__ void edge_count(const int* __restrict__ dst, int m, int* __restrict__ cnt)
{
    int i = blockIdx.x * blockDim.x + threadIdx.x;
    if (i < m) atomicAdd(&cnt[dst[i]], 1);
}

__global__ void scan_block(const int* __restrict__ in, int* __restrict__ out,
                           int* __restrict__ bsums, int N)
{
    __shared__ int s[1024];
    int t = threadIdx.x, idx = blockIdx.x * 1024 + t;
    int v = idx < N ? in[idx] : 0;
    s[t] = v;
    __syncthreads();
    for (int off = 1; off < 1024; off <<= 1) {
        int a = (t >= off) ? s[t - off] : 0;
        __syncthreads();
        s[t] += a;
        __syncthreads();
    }
    if (idx < N) out[idx] = s[t] - v;          // exclusive
    if (t == 1023 && bsums) bsums[blockIdx.x] = s[1023];
}

__global__ void scan_add(int* __restrict__ rp, const int* __restrict__ bs2, int N)
{
    int idx = blockIdx.x * blockDim.x + threadIdx.x;
    if (idx < N) rp[idx] += bs2[idx >> 10];
}

__global__ void edge_scatter(const int* __restrict__ src, const int* __restrict__ dst, int m,
                             const int* __restrict__ rp, int* __restrict__ cnt,
                             int* __restrict__ csr)
{
    int i = blockIdx.x * blockDim.x + threadIdx.x;
    if (i >= m) return;
    int d = dst[i];
    int pos = rp[d] + atomicAdd(&cnt[d], 1);
    csr[pos] = src[i];
}

// ---------------------------------------------------------------------------
// GATv2 aggregation: warp per dst node, online softmax, all-register accum
// ---------------------------------------------------------------------------
__global__ void gat_agg(const int* __restrict__ rp, const int* __restrict__ cs,
                        const float* __restrict__ fs, const float* __restrict__ fd,
                        const float* __restrict__ attn, float* __restrict__ out, int n_out)
{
    int w = (blockIdx.x * blockDim.x + threadIdx.x) >> 5;
    if (w >= n_out) return;
    int lane = threadIdx.x & 31;
    float2 fdv = *(const float2*)&fd[(size_t)w * 64 + lane * 2];
    float2 at  = *(const float2*)&attn[lane * 2];
    float m = -INFINITY, den = 0.f;
    float2 acc = make_float2(0.f, 0.f);
    int beg = rp[w], end = rp[w + 1];
    for (int j = beg; j < end; ++j) {
        int s = __ldg(&cs[j]);
        float2 fv = *(const float2*)&fs[(size_t)s * 64 + lane * 2];
        float ex = lrelu(fv.x + fdv.x, .2f);
        float ey = lrelu(fv.y + fdv.y, .2f);
        float p = ex * at.x + ey * at.y;
#pragma unroll
        for (int o = 16; o; o >>= 1) p += __shfl_xor_sync(0xffffffffu, p, o);
        if (p <= m) {
            float wt = __expf(p - m);
            den += wt; acc.x += wt * fv.x; acc.y += wt * fv.y;
        } else {
            float r = __expf(m - p);   // first edge: exp(-inf)=0
            den = den * r + 1.f;
            acc.x = acc.x * r + fv.x;
            acc.y = acc.y * r + fv.y;
            m = p;
        }
    }
    float2 o;
    if (den > 0.f) { o.x = acc.x / den; o.y = acc.y / den; }
    else           { o.x = 0.f; o.y = 0.f; }
    o.x = lrelu(o.x, .01f); o.y = lrelu(o.y, .01f);
    *(float2*)&out[(size_t)w * 64 + lane * 2] = o;
}

// ---------------------------------------------------------------------------
// Cheb
// ---------------------------------------------------------------------------
__global__ void calc_dinv(const int* __restrict__ rp, float* __restrict__ dinv, int n)
{
    int i = blockIdx.x * blockDim.x + threadIdx.x;
    if (i >= n) return;
    int d = rp[i + 1] - rp[i];
    dinv[i] = rsqrtf((float)(d < 1 ? 1 : d));
}

__global__ void cheb_lhat(const int* __restrict__ rp, const int* __restrict__ cs,
                          const float* __restrict__ dinv, const float* __restrict__ v,
                          const float* __restrict__ extra, const float* __restrict__ lamp,
                          float alpha, float beta, float* __restrict__ out, int n)
{
    int w = (blockIdx.x * blockDim.x + threadIdx.x) >> 5;
    if (w >= n) return;
    int lane = threadIdx.x & 31;
    float c = 2.f / lamp[0];
    float2 v2 = *(const float2*)&v[(size_t)w * 64 + lane * 2];
    float di = dinv[w];
    float2 acc = make_float2(0.f, 0.f);
    int beg = rp[w], end = rp[w + 1];
    for (int j = beg; j < end; ++j) {
        int s = __ldg(&cs[j]);
        float nm = di * dinv[s];
        float2 sv = *(const float2*)&v[(size_t)s * 64 + lane * 2];
        acc.x += nm * sv.x; acc.y += nm * sv.y;
    }
    float2 l;
    l.x = c * (v2.x - acc.x) - v2.x;
    l.y = c * (v2.y - acc.y) - v2.y;
    float2 r;
    if (extra) {
        float2 e2 = *(const float2*)&extra[(size_t)w * 64 + lane * 2];
        r.x = alpha * l.x + beta * e2.x;
        r.y = alpha * l.y + beta * e2.y;
    } else {
        r.x = alpha * l.x; r.y = alpha * l.y;
    }
    *(float2*)&out[(size_t)w * 64 + lane * 2] = r;
}

// ---------------------------------------------------------------------------
// misc elementwise
// ---------------------------------------------------------------------------
__global__ void build_uie(const float* __restrict__ e, float* __restrict__ uie)
{
    size_t idx = (size_t)blockIdx.x * blockDim.x + threadIdx.x;  // float4 index
    if (idx >= (size_t)cfg::NUI * 16) return;
    size_t row = idx >> 4;
    size_t srow = row < (size_t)cfg::PRED ? row : row + (size_t)(cfg::TOTAL - cfg::PRED);
    ((float4*)uie)[idx] = ((const float4*)e)[srow * 16 + (idx & 15)];
}

__global__ void soc_select(const float* __restrict__ i2u, const float* __restrict__ uie,
                           float* __restrict__ soc)
{
    int w = (blockIdx.x * blockDim.x + threadIdx.x) >> 5;
    if (w >= cfg::PRED) return;
    int lane = threadIdx.x & 31;
    float2 a = *(const float2*)&i2u[(size_t)w * 64 + lane * 2];
    float p = a.x + a.y;
#pragma unroll
    for (int o = 16; o; o >>= 1) p += __shfl_xor_sync(0xffffffffu, p, o);
    float2 o2 = (p != 0.f) ? a : *(const float2*)&uie[(size_t)w * 64 + lane * 2];
    *(float2*)&soc[(size_t)w * 64 + lane * 2] = o2;
}

__global__ void hm_soft(const float* __restrict__ hA, const float* __restrict__ hB,
                        float* __restrict__ out)
{
    int w = (blockIdx.x * blockDim.x + threadIdx.x) >> 5;
    if (w >= cfg::PRED) return;
    int lane = threadIdx.x & 31;
    float2 a = *(const float2*)&hA[(size_t)w * 64 + lane * 2];
    float2 b = *(const float2*)&hB[(size_t)w * 64 + lane * 2];
    float mx = fmaxf(a.x, a.y);
#pragma unroll
    for (int o = 16; o; o >>= 1) mx = fmaxf(mx, __shfl_xor_sync(0xffffffffu, mx, o));
    float ex = __expf(a.x - mx), ey = __expf(a.y - mx);
    float s = ex + ey;
#pragma unroll
    for (int o = 16; o; o >>= 1) s += __shfl_xor_sync(0xffffffffu, s, o);
    float inv = 1.f / s;
    float2 o2;
    o2.x = a.x * b.x * ex * inv;
    o2.y = a.y * b.y * ey * inv;
    *(float2*)&out[(size_t)w * 64 + lane * 2] = o2;
}

// ---------------------------------------------------------------------------
// host orchestration
// ---------------------------------------------------------------------------
namespace {
inline int divup(int a, int b) { return (a + b - 1) / b; }

struct Ctx {
    float* f;
    int*   i;
};

void csr_build(const Ctx& c, int g, const int* src, const int* dst, int m, int n)
{
    using namespace cfg;
    int* cnt = c.i + I_CNT + g * RPSZ;
    int* rp  = c.i + I_RP  + g * RPSZ;
    int* bs  = c.i + I_BS  + g * 512;
    int* bs2 = c.i + I_BS2 + g * 512;
    int* csr = c.i + I_CSR + CSR_OFF[g];
    int N = n + 1;
    cudaMemsetAsync(cnt, 0, sizeof(int) * N);
    edge_count<<<divup(m, 256), 256>>>(dst, m, cnt);
    int nb = divup(N, 1024);
    scan_block<<<nb, 1024>>>(cnt, rp, bs, N);
    scan_block<<<1, 1024>>>(bs, bs2, nullptr, nb);
    scan_add<<<divup(N, 256), 256>>>(rp, bs2, N);
    cudaMemsetAsync(cnt, 0, sizeof(int) * N);
    edge_scatter<<<divup(m, 256), 256>>>(src, dst, m, rp, cnt, csr);
}

void run_bn(const Ctx& c, const float* x, const float* g, const float* b,
            float* y, int n, int leaky)
{
    using namespace cfg;
    float* stats = c.f + O_STATS;
    cudaMemsetAsync(stats, 0, 128 * sizeof(float));
    bn_stats<<<512, 256>>>(x, stats, n);
    size_t tot = (size_t)n * 64;
    bn_apply<<<(int)divup((int)tot, 256), 256>>>(x, stats, g, b, y, n, leaky);
}

void run_gemm(const float* X, const float* W, const float* bias, float* Y, int n, int flags)
{
    gemm64<<<divup(n, 128), 128, GEMM_SMEM>>>(X, W, bias, Y, n, flags);
}

void run_gat(const Ctx& c, int li, int g, const float* x, int n, int n_out,
             const float* Wl, const float* bl, const float* Wr, const float* br,
             const float* attn, float* out)
{
    using namespace cfg;
    float* fs = c.f + O_FS;
    float* fd = c.f + O_FD;
    run_gemm(x, Wl + (size_t)li * 4096, bl + (size_t)li * 64, fs, n, 1);
    run_gemm(x, Wr + (size_t)li * 4096, br + (size_t)li * 64, fd, n_out, 1);
    gat_agg<<<divup(n_out * 32, 256), 256>>>(c.i + I_RP + g * RPSZ,
                                             c.i + I_CSR + CSR_OFF[g], fs, fd,
                                             attn + (size_t)li * 64, out, n_out);
}

void run_mlp(const Ctx& c, int li, const float* A, const float* B,
             const float* Wm, const float* bm, const float* gm, const float* betam,
             float* out)
{
    using namespace cfg;
    float* tmp = c.f + O_TMP;
    run_gemm(A, Wm + (size_t)li * 8192,        bm + (size_t)li * 64, tmp, PRED, 1);
    run_gemm(B, Wm + (size_t)li * 8192 + 4096, nullptr,              tmp, PRED, 0);
    run_bn(c, tmp, gm + (size_t)li * 64, betam + (size_t)li * 64, out, PRED, 1);
}

void run_cheb(const Ctx& c, int g, const float* x, const float* chebW, const float* chebB,
              const float* lamp, float* out)
{
    using namespace cfg;
    float* t1 = c.f + O_T1;
    float* t2 = c.f + O_T2;
    const float* dinv = c.f + O_DINV;
    const int* rp = c.i + I_RP + g * RPSZ;
    const int* cs = c.i + I_CSR + CSR_OFF[g];
    int gr = divup(TOTAL * 32, 256);
    cheb_lhat<<<gr, 256>>>(rp, cs, dinv, x, nullptr, lamp, 1.f, 0.f, t1, TOTAL);
    cheb_lhat<<<gr, 256>>>(rp, cs, dinv, t1, x, lamp, 2.f, -1.f, t2, TOTAL);
    run_gemm(x,  chebW,        chebB,   out, TOTAL, 1);
    run_gemm(t1, chebW + 4096, nullptr, out, TOTAL, 0);
    run_gemm(t2, chebW + 8192, nullptr, out, TOTAL, 2);  // acc + leaky
}
}  // namespace

extern "C" void kernel_launch(void* const* d_in, const int* in_sizes, int n_in,
                              void* d_out, int out_size)
{
    using namespace cfg;
    Ctx c;
    cudaGetSymbolAddress((void**)&c.f, g_f);
    cudaGetSymbolAddress((void**)&c.i, g_i);
    cudaFuncSetAttribute(gemm64, cudaFuncAttributeMaxDynamicSharedMemorySize, GEMM_SMEM);

    const float* emb    = (const float*)d_in[0];
    const float* bn0_g  = (const float*)d_in[1];
    const float* bn0_b  = (const float*)d_in[2];
    const float* gat_Wl = (const float*)d_in[3];
    const float* gat_bl = (const float*)d_in[4];
    const float* gat_Wr = (const float*)d_in[5];
    const float* gat_br = (const float*)d_in[6];
    const float* gat_at = (const float*)d_in[7];
    const float* cheb_W = (const float*)d_in[8];
    const float* cheb_b = (const float*)d_in[9];
    const float* mlp_W  = (const float*)d_in[10];
    const float* mlp_b  = (const float*)d_in[11];
    const float* mlp_g  = (const float*)d_in[12];
    const float* mlp_be = (const float*)d_in[13];
    const float* lamp   = (const float*)d_in[14];
    const int* u2i_src = (const int*)d_in[15]; const int* u2i_dst = (const int*)d_in[16];
    const int* rc_src  = (const int*)d_in[17]; const int* rc_dst  = (const int*)d_in[18];
    const int* i2u_src = (const int*)d_in[19]; const int* i2u_dst = (const int*)d_in[20];
    const int* sn_src  = (const int*)d_in[22]; const int* sn_dst  = (const int*)d_in[23];
    const int* snn_src = (const int*)d_in[24]; const int* snn_dst = (const int*)d_in[25];
    const int m_u2i = in_sizes[15], m_rc = in_sizes[17], m_i2u = in_sizes[19];
    const int m_sn = in_sizes[22], m_snn = in_sizes[24];

    float* E   = c.f + O_E;
    float* UIE = c.f + O_UIE;
    float* G0  = c.f + O_G0;
    float* G1  = c.f + O_G1;
    float* I2U = c.f + O_I2U;
    float* SOC = c.f + O_SOC;
    float* SIE = c.f + O_SIE;
    float* UIM = c.f + O_UIM;
    float* HUP = c.f + O_HUP;
    float* HUS = c.f + O_HUS;
    float* SP  = c.f + O_SP;
    float* USE = c.f + O_USE;
    float* H   = c.f + O_H;
    float* CH2 = c.f + O_CH2;
    float* out = (float*)d_out;

    // ---- BN0 over full emb ----
    run_bn(c, emb, bn0_g, bn0_b, E, NODES, 0);

    // ---- uie = concat([e[:PRED], e[-ITEM:]]) ----
    build_uie<<<divup(NUI * 16, 256), 256>>>(E, UIE);

    // ---- GAT0: u2i over uie ----
    csr_build(c, 0, u2i_src, u2i_dst, m_u2i, NUI);
    run_gat(c, 0, 0, UIE, NUI, NUI, gat_Wl, gat_bl, gat_Wr, gat_br, gat_at, G0);

    // ---- GAT1: rc over u2i_emb, only [:PRED] consumed ----
    csr_build(c, 1, rc_src, rc_dst, m_rc, NUI);
    run_gat(c, 1, 1, G0, NUI, PRED, gat_Wl, gat_bl, gat_Wr, gat_br, gat_at, G1);

    // ---- GAT2: i2u over su = uie[:PRED] ----
    csr_build(c, 2, i2u_src, i2u_dst, m_i2u, PRED);
    run_gat(c, 2, 2, UIE, PRED, PRED, gat_Wl, gat_bl, gat_Wr, gat_br, gat_at, I2U);

    // ---- soc ----
    soc_select<<<divup(PRED * 32, 256), 256>>>(I2U, UIE, SOC);

    // ---- GAT3: sn over soc ----
    csr_build(c, 3, sn_src, sn_dst, m_sn, PRED);
    run_gat(c, 3, 3, SOC, PRED, PRED, gat_Wl, gat_bl, gat_Wr, gat_br, gat_at, SIE);

    // ---- mlp0 ----
    run_mlp(c, 0, G1, SIE, mlp_W, mlp_b, mlp_g, mlp_be, UIM);

    // ---- snn graph: cheb x2 + GAT4 ----
    csr_build(c, 4, snn_src, snn_dst, m_snn, TOTAL);
    calc_dinv<<<divup(TOTAL, 256), 256>>>(c.i + I_RP + 4 * RPSZ, c.f + O_DINV, TOTAL);
    run_cheb(c, 4, E, cheb_W, cheb_b, lamp, H);
    run_cheb(c, 4, H, cheb_W, cheb_b, lamp, CH2);
    run_gat(c, 4, 4, CH2, TOTAL, PRED, gat_Wl, gat_bl, gat_Wr, gat_br, gat_at, USE);

    // ---- mlp1 / mlp2 ----
    run_mlp(c, 1, UIM, E, mlp_W, mlp_b, mlp_g, mlp_be, HUP);
    run_mlp(c, 2, USE, E, mlp_W, mlp_b, mlp_g, mlp_be, HUS);

    // ---- outputs ----
    hm_soft<<<divup(PRED * 32, 256), 256>>>(HUP, HUS, SP);
    run_mlp(c, 3, SP, HUP, mlp_W, mlp_b, mlp_g, mlp_be, out);

    hm_soft<<<divup(PRED * 32, 256), 256>>>(HUS, HUP, SP);
    run_mlp(c, 4, SP, HUS, mlp_W, mlp_b, mlp_g, mlp_be, out + S_PRED);
}

// round 11
// speedup vs baseline: 1.1424x; 1.1424x over previous
#include <cuda_runtime.h>
#include <math.h>
#include <stdint.h>

// ---------------------------------------------------------------------------
// Problem constants
// ---------------------------------------------------------------------------
namespace cfg {
constexpr int PRED = 100000, TOTAL = 120000, NUI = 200000, NODES = 220000;
constexpr float EPS = 1e-5f;

constexpr size_t S_NODE = (size_t)NODES * 64;
constexpr size_t S_NUI  = (size_t)NUI * 64;
constexpr size_t S_PRED = (size_t)PRED * 64;
constexpr size_t S_TOT  = (size_t)TOTAL * 64;

// float pool offsets
constexpr size_t O_E    = 0;
constexpr size_t O_UIE  = O_E + S_NODE;
constexpr size_t O_FS   = O_UIE + S_NUI;
constexpr size_t O_FD   = O_FS + S_NUI;
constexpr size_t O_G0   = O_FD + S_NUI;
constexpr size_t O_G1   = O_G0 + S_NUI;
constexpr size_t O_I2U  = O_G1 + S_PRED;
constexpr size_t O_SOC  = O_I2U + S_PRED;
constexpr size_t O_SIE  = O_SOC + S_PRED;
constexpr size_t O_UIM  = O_SIE + S_PRED;
constexpr size_t O_TMP  = O_UIM + S_PRED;
constexpr size_t O_HUP  = O_TMP + S_PRED;
constexpr size_t O_HUS  = O_HUP + S_PRED;
constexpr size_t O_SP   = O_HUS + S_PRED;
constexpr size_t O_USE  = O_SP + S_PRED;
constexpr size_t O_T1   = O_USE + S_PRED;
constexpr size_t O_T2   = O_T1 + S_TOT;
constexpr size_t O_H    = O_T2 + S_TOT;
constexpr size_t O_CH2  = O_H + S_TOT;
constexpr size_t O_DINV = O_CH2 + S_TOT;
constexpr size_t O_STATS= O_DINV + TOTAL;
constexpr size_t FPOOL  = O_STATS + 128;

// int pool: per-graph CSR structures
constexpr int  NG = 5;
constexpr size_t RPSZ  = 200002;
constexpr size_t I_RP  = 0;                       // 5 x RPSZ
constexpr size_t I_CNT = I_RP + NG * RPSZ;        // 5 x RPSZ
constexpr size_t I_BS  = I_CNT + NG * RPSZ;       // 5 x 512
constexpr size_t I_BS2 = I_BS + NG * 512;         // 5 x 512
constexpr size_t I_CSR = I_BS2 + NG * 512;        // 6.5M
constexpr size_t CSR_OFF[5] = {0, 1500000, 3000000, 4000000, 5000000};
constexpr size_t IPOOL = I_CSR + 6500000;
}  // namespace cfg

__device__ float g_f[cfg::FPOOL];
__device__ int   g_i[cfg::IPOOL];

// ---------------------------------------------------------------------------
// helpers
// ---------------------------------------------------------------------------
__device__ __forceinline__ float lrelu(float x, float s) { return x > 0.f ? x : s * x; }

// ---------------------------------------------------------------------------
// GEMM: Y[n x 64] = act( base + X[n x 64] @ W[64 x 64] )   (R1 version, 1802us)
// flags bit0: base = bias (else accumulate into existing Y)
// flags bit1: leaky_relu(0.01)
// BM=64, BN=64, 128 threads, TM=8 x TN=4
// ---------------------------------------------------------------------------
__global__ __launch_bounds__(128) void gemm64(
    const float* __restrict__ X, const float* __restrict__ W,
    const float* __restrict__ bias, float* __restrict__ Y, int n, int flags)
{
    __shared__ float Xs[64 * 68];   // [k][r], stride 68
    __shared__ float Ws[64 * 64];   // [k][c]
    const int t = threadIdx.x;
    const int m0 = blockIdx.x * 64;

    {
        const float4* W4 = (const float4*)W;
        float4* Ws4 = (float4*)Ws;
#pragma unroll
        for (int i = 0; i < 8; i++) Ws4[i * 128 + t] = W4[i * 128 + t];
    }
#pragma unroll
    for (int i = 0; i < 8; i++) {
        int lin4 = i * 128 + t;            // 0..1023
        int r = lin4 >> 4, k4 = lin4 & 15;
        float4 v = make_float4(0.f, 0.f, 0.f, 0.f);
        if (m0 + r < n) v = *(const float4*)&X[(size_t)(m0 + r) * 64 + k4 * 4];
        Xs[(k4 * 4 + 0) * 68 + r] = v.x;
        Xs[(k4 * 4 + 1) * 68 + r] = v.y;
        Xs[(k4 * 4 + 2) * 68 + r] = v.z;
        Xs[(k4 * 4 + 3) * 68 + r] = v.w;
    }
    __syncthreads();

    const int tx = t & 15, ty = t >> 4;
    float acc[8][4];
#pragma unroll
    for (int i = 0; i < 8; i++)
#pragma unroll
        for (int j = 0; j < 4; j++) acc[i][j] = 0.f;

#pragma unroll 8
    for (int k = 0; k < 64; k++) {
        float4 b  = *(const float4*)&Ws[k * 64 + tx * 4];
        float4 a0 = *(const float4*)&Xs[k * 68 + ty * 8];
        float4 a1 = *(const float4*)&Xs[k * 68 + ty * 8 + 4];
        float av[8] = {a0.x, a0.y, a0.z, a0.w, a1.x, a1.y, a1.z, a1.w};
        float bv[4] = {b.x, b.y, b.z, b.w};
#pragma unroll
        for (int i = 0; i < 8; i++)
#pragma unroll
            for (int j = 0; j < 4; j++) acc[i][j] += av[i] * bv[j];
    }

    const bool init = flags & 1, lk = flags & 2;
    float4 bb = make_float4(0.f, 0.f, 0.f, 0.f);
    if (init) bb = *(const float4*)&bias[tx * 4];
#pragma unroll
    for (int i = 0; i < 8; i++) {
        int row = m0 + ty * 8 + i;
        if (row >= n) break;
        float4 base = init ? bb : *(const float4*)&Y[(size_t)row * 64 + tx * 4];
        float4 o;
        o.x = base.x + acc[i][0];
        o.y = base.y + acc[i][1];
        o.z = base.z + acc[i][2];
        o.w = base.w + acc[i][3];
        if (lk) { o.x = lrelu(o.x, .01f); o.y = lrelu(o.y, .01f); o.z = lrelu(o.z, .01f); o.w = lrelu(o.w, .01f); }
        *(float4*)&Y[(size_t)row * 64 + tx * 4] = o;
    }
}

// ---------------------------------------------------------------------------
// BatchNorm
// ---------------------------------------------------------------------------
__global__ void bn_stats(const float* __restrict__ x, float* __restrict__ stats, int n)
{
    const int col = threadIdx.x & 63, rg = threadIdx.x >> 6;  // 256 threads
    float s = 0.f, q = 0.f;
    for (int r = blockIdx.x * 4 + rg; r < n; r += gridDim.x * 4) {
        float v = x[(size_t)r * 64 + col];
        s += v; q += v * v;
    }
    __shared__ float sh[2][4][64];
    sh[0][rg][col] = s; sh[1][rg][col] = q;
    __syncthreads();
    if (rg == 0) {
        s = sh[0][0][col] + sh[0][1][col] + sh[0][2][col] + sh[0][3][col];
        q = sh[1][0][col] + sh[1][1][col] + sh[1][2][col] + sh[1][3][col];
        atomicAdd(&stats[col], s);
        atomicAdd(&stats[64 + col], q);
    }
}

__global__ void bn_apply(const float* __restrict__ x, const float* __restrict__ stats,
                         const float* __restrict__ g, const float* __restrict__ b,
                         float* __restrict__ y, int n, int leaky)
{
    size_t idx = (size_t)blockIdx.x * blockDim.x + threadIdx.x;
    size_t tot = (size_t)n * 64;
    if (idx >= tot) return;
    int col = idx & 63;
    float mu  = stats[col] / (float)n;
    float var = stats[64 + col] / (float)n - mu * mu;
    float sc = rsqrtf(var + cfg::EPS) * g[col];
    float v = (x[idx] - mu) * sc + b[col];
    y[idx] = leaky ? lrelu(v, .01f) : v;
}

// ---------------------------------------------------------------------------
// CSR build
// ---------------------------------------------------------------------------
__global__ void edge_count(const int* __restrict__ dst, int m, int* __restrict__ cnt)
{
    int i = blockIdx.x * blockDim.x + threadIdx.x;
    if (i < m) atomicAdd(&cnt[dst[i]], 1);
}

__global__ void scan_block(const int* __restrict__ in, int* __restrict__ out,
                           int* __restrict__ bsums, int N)
{
    __shared__ int s[1024];
    int t = threadIdx.x, idx = blockIdx.x * 1024 + t;
    int v = idx < N ? in[idx] : 0;
    s[t] = v;
    __syncthreads();
    for (int off = 1; off < 1024; off <<= 1) {
        int a = (t >= off) ? s[t - off] : 0;
        __syncthreads();
        s[t] += a;
        __syncthreads();
    }
    if (idx < N) out[idx] = s[t] - v;          // exclusive
    if (t == 1023 && bsums) bsums[blockIdx.x] = s[1023];
}

__global__ void scan_add(int* __restrict__ rp, const int* __restrict__ bs2, int N)
{
    int idx = blockIdx.x * blockDim.x + threadIdx.x;
    if (idx < N) rp[idx] += bs2[idx >> 10];
}

__global__ void edge_scatter(const int* __restrict__ src, const int* __restrict__ dst, int m,
                             const int* __restrict__ rp, int* __restrict__ cnt,
                             int* __restrict__ csr)
{
    int i = blockIdx.x * blockDim.x + threadIdx.x;
    if (i >= m) return;
    int d = dst[i];
    int pos = rp[d] + atomicAdd(&cnt[d], 1);
    csr[pos] = src[i];
}

// ---------------------------------------------------------------------------
// GATv2 aggregation: warp per dst node, online softmax, all-register accum
// ---------------------------------------------------------------------------
__global__ void gat_agg(const int* __restrict__ rp, const int* __restrict__ cs,
                        const float* __restrict__ fs, const float* __restrict__ fd,
                        const float* __restrict__ attn, float* __restrict__ out, int n_out)
{
    int w = (blockIdx.x * blockDim.x + threadIdx.x) >> 5;
    if (w >= n_out) return;
    int lane = threadIdx.x & 31;
    float2 fdv = *(const float2*)&fd[(size_t)w * 64 + lane * 2];
    float2 at  = *(const float2*)&attn[lane * 2];
    float m = -INFINITY, den = 0.f;
    float2 acc = make_float2(0.f, 0.f);
    int beg = rp[w], end = rp[w + 1];
    for (int j = beg; j < end; ++j) {
        int s = __ldg(&cs[j]);
        float2 fv = *(const float2*)&fs[(size_t)s * 64 + lane * 2];
        float ex = lrelu(fv.x + fdv.x, .2f);
        float ey = lrelu(fv.y + fdv.y, .2f);
        float p = ex * at.x + ey * at.y;
#pragma unroll
        for (int o = 16; o; o >>= 1) p += __shfl_xor_sync(0xffffffffu, p, o);
        if (p <= m) {
            float wt = __expf(p - m);
            den += wt; acc.x += wt * fv.x; acc.y += wt * fv.y;
        } else {
            float r = __expf(m - p);   // first edge: exp(-inf)=0
            den = den * r + 1.f;
            acc.x = acc.x * r + fv.x;
            acc.y = acc.y * r + fv.y;
            m = p;
        }
    }
    float2 o;
    if (den > 0.f) { o.x = acc.x / den; o.y = acc.y / den; }
    else           { o.x = 0.f; o.y = 0.f; }
    o.x = lrelu(o.x, .01f); o.y = lrelu(o.y, .01f);
    *(float2*)&out[(size_t)w * 64 + lane * 2] = o;
}

// ---------------------------------------------------------------------------
// Cheb
// ---------------------------------------------------------------------------
__global__ void calc_dinv(const int* __restrict__ rp, float* __restrict__ dinv, int n)
{
    int i = blockIdx.x * blockDim.x + threadIdx.x;
    if (i >= n) return;
    int d = rp[i + 1] - rp[i];
    dinv[i] = rsqrtf((float)(d < 1 ? 1 : d));
}

__global__ void cheb_lhat(const int* __restrict__ rp, const int* __restrict__ cs,
                          const float* __restrict__ dinv, const float* __restrict__ v,
                          const float* __restrict__ extra, const float* __restrict__ lamp,
                          float alpha, float beta, float* __restrict__ out, int n)
{
    int w = (blockIdx.x * blockDim.x + threadIdx.x) >> 5;
    if (w >= n) return;
    int lane = threadIdx.x & 31;
    float c = 2.f / lamp[0];
    float2 v2 = *(const float2*)&v[(size_t)w * 64 + lane * 2];
    float di = dinv[w];
    float2 acc = make_float2(0.f, 0.f);
    int beg = rp[w], end = rp[w + 1];
    for (int j = beg; j < end; ++j) {
        int s = __ldg(&cs[j]);
        float nm = di * dinv[s];
        float2 sv = *(const float2*)&v[(size_t)s * 64 + lane * 2];
        acc.x += nm * sv.x; acc.y += nm * sv.y;
    }
    float2 l;
    l.x = c * (v2.x - acc.x) - v2.x;
    l.y = c * (v2.y - acc.y) - v2.y;
    float2 r;
    if (extra) {
        float2 e2 = *(const float2*)&extra[(size_t)w * 64 + lane * 2];
        r.x = alpha * l.x + beta * e2.x;
        r.y = alpha * l.y + beta * e2.y;
    } else {
        r.x = alpha * l.x; r.y = alpha * l.y;
    }
    *(float2*)&out[(size_t)w * 64 + lane * 2] = r;
}

// ---------------------------------------------------------------------------
// misc elementwise
// ---------------------------------------------------------------------------
__global__ void build_uie(const float* __restrict__ e, float* __restrict__ uie)
{
    size_t idx = (size_t)blockIdx.x * blockDim.x + threadIdx.x;  // float4 index
    if (idx >= (size_t)cfg::NUI * 16) return;
    size_t row = idx >> 4;
    size_t srow = row < (size_t)cfg::PRED ? row : row + (size_t)(cfg::TOTAL - cfg::PRED);
    ((float4*)uie)[idx] = ((const float4*)e)[srow * 16 + (idx & 15)];
}

__global__ void soc_select(const float* __restrict__ i2u, const float* __restrict__ uie,
                           float* __restrict__ soc)
{
    int w = (blockIdx.x * blockDim.x + threadIdx.x) >> 5;
    if (w >= cfg::PRED) return;
    int lane = threadIdx.x & 31;
    float2 a = *(const float2*)&i2u[(size_t)w * 64 + lane * 2];
    float p = a.x + a.y;
#pragma unroll
    for (int o = 16; o; o >>= 1) p += __shfl_xor_sync(0xffffffffu, p, o);
    float2 o2 = (p != 0.f) ? a : *(const float2*)&uie[(size_t)w * 64 + lane * 2];
    *(float2*)&soc[(size_t)w * 64 + lane * 2] = o2;
}

__global__ void hm_soft(const float* __restrict__ hA, const float* __restrict__ hB,
                        float* __restrict__ out)
{
    int w = (blockIdx.x * blockDim.x + threadIdx.x) >> 5;
    if (w >= cfg::PRED) return;
    int lane = threadIdx.x & 31;
    float2 a = *(const float2*)&hA[(size_t)w * 64 + lane * 2];
    float2 b = *(const float2*)&hB[(size_t)w * 64 + lane * 2];
    float mx = fmaxf(a.x, a.y);
#pragma unroll
    for (int o = 16; o; o >>= 1) mx = fmaxf(mx, __shfl_xor_sync(0xffffffffu, mx, o));
    float ex = __expf(a.x - mx), ey = __expf(a.y - mx);
    float s = ex + ey;
#pragma unroll
    for (int o = 16; o; o >>= 1) s += __shfl_xor_sync(0xffffffffu, s, o);
    float inv = 1.f / s;
    float2 o2;
    o2.x = a.x * b.x * ex * inv;
    o2.y = a.y * b.y * ey * inv;
    *(float2*)&out[(size_t)w * 64 + lane * 2] = o2;
}

// ---------------------------------------------------------------------------
// host orchestration
// ---------------------------------------------------------------------------
namespace {
inline int divup(int a, int b) { return (a + b - 1) / b; }

struct Ctx {
    float* f;
    int*   i;
};

// side stream + events, created once on the (non-captured) correctness call
// and reused for every subsequent call; per-call launch sequence is identical.
cudaStream_t g_side = nullptr;
cudaEvent_t  g_ev0 = nullptr;
cudaEvent_t  g_evc[cfg::NG] = {};

void ensure_sync_objs()
{
    if (g_side) return;
    cudaStreamCaptureStatus st = cudaStreamCaptureStatusNone;
    cudaStreamIsCapturing(0, &st);
    if (st != cudaStreamCaptureStatusNone) return;  // never create during capture
    cudaStreamCreateWithFlags(&g_side, cudaStreamNonBlocking);
    cudaEventCreateWithFlags(&g_ev0, cudaEventDisableTiming);
    for (int g = 0; g < cfg::NG; g++)
        cudaEventCreateWithFlags(&g_evc[g], cudaEventDisableTiming);
}

void csr_build(const Ctx& c, int g, const int* src, const int* dst, int m, int n,
               cudaStream_t st)
{
    using namespace cfg;
    int* cnt = c.i + I_CNT + g * RPSZ;
    int* rp  = c.i + I_RP  + g * RPSZ;
    int* bs  = c.i + I_BS  + g * 512;
    int* bs2 = c.i + I_BS2 + g * 512;
    int* csr = c.i + I_CSR + CSR_OFF[g];
    int N = n + 1;
    cudaMemsetAsync(cnt, 0, sizeof(int) * N, st);
    edge_count<<<divup(m, 256), 256, 0, st>>>(dst, m, cnt);
    int nb = divup(N, 1024);
    scan_block<<<nb, 1024, 0, st>>>(cnt, rp, bs, N);
    scan_block<<<1, 1024, 0, st>>>(bs, bs2, nullptr, nb);
    scan_add<<<divup(N, 256), 256, 0, st>>>(rp, bs2, N);
    cudaMemsetAsync(cnt, 0, sizeof(int) * N, st);
    edge_scatter<<<divup(m, 256), 256, 0, st>>>(src, dst, m, rp, cnt, csr);
}

void run_bn(const Ctx& c, const float* x, const float* g, const float* b,
            float* y, int n, int leaky)
{
    using namespace cfg;
    float* stats = c.f + O_STATS;
    cudaMemsetAsync(stats, 0, 128 * sizeof(float));
    bn_stats<<<512, 256>>>(x, stats, n);
    size_t tot = (size_t)n * 64;
    bn_apply<<<(int)divup((int)tot, 256), 256>>>(x, stats, g, b, y, n, leaky);
}

void run_gemm(const float* X, const float* W, const float* bias, float* Y, int n, int flags)
{
    gemm64<<<divup(n, 64), 128>>>(X, W, bias, Y, n, flags);
}

void run_gat(const Ctx& c, int li, int g, const float* x, int n, int n_out,
             const float* Wl, const float* bl, const float* Wr, const float* br,
             const float* attn, float* out)
{
    using namespace cfg;
    float* fs = c.f + O_FS;
    float* fd = c.f + O_FD;
    run_gemm(x, Wl + (size_t)li * 4096, bl + (size_t)li * 64, fs, n, 1);
    run_gemm(x, Wr + (size_t)li * 4096, br + (size_t)li * 64, fd, n_out, 1);
    if (g_side) cudaStreamWaitEvent(0, g_evc[g], 0);   // CSR must be ready
    gat_agg<<<divup(n_out * 32, 256), 256>>>(c.i + I_RP + g * RPSZ,
                                             c.i + I_CSR + CSR_OFF[g], fs, fd,
                                             attn + (size_t)li * 64, out, n_out);
}

void run_mlp(const Ctx& c, int li, const float* A, const float* B,
             const float* Wm, const float* bm, const float* gm, const float* betam,
             float* out)
{
    using namespace cfg;
    float* tmp = c.f + O_TMP;
    run_gemm(A, Wm + (size_t)li * 8192,        bm + (size_t)li * 64, tmp, PRED, 1);
    run_gemm(B, Wm + (size_t)li * 8192 + 4096, nullptr,              tmp, PRED, 0);
    run_bn(c, tmp, gm + (size_t)li * 64, betam + (size_t)li * 64, out, PRED, 1);
}

void run_cheb(const Ctx& c, int g, const float* x, const float* chebW, const float* chebB,
              const float* lamp, float* out)
{
    using namespace cfg;
    float* t1 = c.f + O_T1;
    float* t2 = c.f + O_T2;
    const float* dinv = c.f + O_DINV;
    const int* rp = c.i + I_RP + g * RPSZ;
    const int* cs = c.i + I_CSR + CSR_OFF[g];
    int gr = divup(TOTAL * 32, 256);
    cheb_lhat<<<gr, 256>>>(rp, cs, dinv, x, nullptr, lamp, 1.f, 0.f, t1, TOTAL);
    cheb_lhat<<<gr, 256>>>(rp, cs, dinv, t1, x, lamp, 2.f, -1.f, t2, TOTAL);
    run_gemm(x,  chebW,        chebB,   out, TOTAL, 1);
    run_gemm(t1, chebW + 4096, nullptr, out, TOTAL, 0);
    run_gemm(t2, chebW + 8192, nullptr, out, TOTAL, 2);  // acc + leaky
}
}  // namespace

extern "C" void kernel_launch(void* const* d_in, const int* in_sizes, int n_in,
                              void* d_out, int out_size)
{
    using namespace cfg;
    Ctx c;
    cudaGetSymbolAddress((void**)&c.f, g_f);
    cudaGetSymbolAddress((void**)&c.i, g_i);
    ensure_sync_objs();

    const float* emb    = (const float*)d_in[0];
    const float* bn0_g  = (const float*)d_in[1];
    const float* bn0_b  = (const float*)d_in[2];
    const float* gat_Wl = (const float*)d_in[3];
    const float* gat_bl = (const float*)d_in[4];
    const float* gat_Wr = (const float*)d_in[5];
    const float* gat_br = (const float*)d_in[6];
    const float* gat_at = (const float*)d_in[7];
    const float* cheb_W = (const float*)d_in[8];
    const float* cheb_b = (const float*)d_in[9];
    const float* mlp_W  = (const float*)d_in[10];
    const float* mlp_b  = (const float*)d_in[11];
    const float* mlp_g  = (const float*)d_in[12];
    const float* mlp_be = (const float*)d_in[13];
    const float* lamp   = (const float*)d_in[14];
    const int* u2i_src = (const int*)d_in[15]; const int* u2i_dst = (const int*)d_in[16];
    const int* rc_src  = (const int*)d_in[17]; const int* rc_dst  = (const int*)d_in[18];
    const int* i2u_src = (const int*)d_in[19]; const int* i2u_dst = (const int*)d_in[20];
    const int* sn_src  = (const int*)d_in[22]; const int* sn_dst  = (const int*)d_in[23];
    const int* snn_src = (const int*)d_in[24]; const int* snn_dst = (const int*)d_in[25];
    const int m_u2i = in_sizes[15], m_rc = in_sizes[17], m_i2u = in_sizes[19];
    const int m_sn = in_sizes[22], m_snn = in_sizes[24];

    float* E   = c.f + O_E;
    float* UIE = c.f + O_UIE;
    float* G0  = c.f + O_G0;
    float* G1  = c.f + O_G1;
    float* I2U = c.f + O_I2U;
    float* SOC = c.f + O_SOC;
    float* SIE = c.f + O_SIE;
    float* UIM = c.f + O_UIM;
    float* HUP = c.f + O_HUP;
    float* HUS = c.f + O_HUS;
    float* SP  = c.f + O_SP;
    float* USE = c.f + O_USE;
    float* H   = c.f + O_H;
    float* CH2 = c.f + O_CH2;
    float* out = (float*)d_out;

    // ---- fork side stream; build ALL CSRs there, overlapped with dense chain
    if (g_side) {
        cudaEventRecord(g_ev0, 0);
        cudaStreamWaitEvent(g_side, g_ev0, 0);
        csr_build(c, 0, u2i_src, u2i_dst, m_u2i, NUI,  g_side); cudaEventRecord(g_evc[0], g_side);
        csr_build(c, 1, rc_src,  rc_dst,  m_rc,  NUI,  g_side); cudaEventRecord(g_evc[1], g_side);
        csr_build(c, 2, i2u_src, i2u_dst, m_i2u, PRED, g_side); cudaEventRecord(g_evc[2], g_side);
        csr_build(c, 3, sn_src,  sn_dst,  m_sn,  PRED, g_side); cudaEventRecord(g_evc[3], g_side);
        csr_build(c, 4, snn_src, snn_dst, m_snn, TOTAL, g_side); cudaEventRecord(g_evc[4], g_side);
    } else {
        csr_build(c, 0, u2i_src, u2i_dst, m_u2i, NUI,  0);
        csr_build(c, 1, rc_src,  rc_dst,  m_rc,  NUI,  0);
        csr_build(c, 2, i2u_src, i2u_dst, m_i2u, PRED, 0);
        csr_build(c, 3, sn_src,  sn_dst,  m_sn,  PRED, 0);
        csr_build(c, 4, snn_src, snn_dst, m_snn, TOTAL, 0);
    }

    // ---- BN0 over full emb ----
    run_bn(c, emb, bn0_g, bn0_b, E, NODES, 0);

    // ---- uie = concat([e[:PRED], e[-ITEM:]]) ----
    build_uie<<<divup(NUI * 16, 256), 256>>>(E, UIE);

    // ---- GAT0: u2i over uie ----
    run_gat(c, 0, 0, UIE, NUI, NUI, gat_Wl, gat_bl, gat_Wr, gat_br, gat_at, G0);

    // ---- GAT1: rc over u2i_emb, only [:PRED] consumed ----
    run_gat(c, 1, 1, G0, NUI, PRED, gat_Wl, gat_bl, gat_Wr, gat_br, gat_at, G1);

    // ---- GAT2: i2u over su = uie[:PRED] ----
    run_gat(c, 2, 2, UIE, PRED, PRED, gat_Wl, gat_bl, gat_Wr, gat_br, gat_at, I2U);

    // ---- soc ----
    soc_select<<<divup(PRED * 32, 256), 256>>>(I2U, UIE, SOC);

    // ---- GAT3: sn over soc ----
    run_gat(c, 3, 3, SOC, PRED, PRED, gat_Wl, gat_bl, gat_Wr, gat_br, gat_at, SIE);

    // ---- mlp0 ----
    run_mlp(c, 0, G1, SIE, mlp_W, mlp_b, mlp_g, mlp_be, UIM);

    // ---- snn graph: cheb x2 + GAT4 ----
    if (g_side) cudaStreamWaitEvent(0, g_evc[4], 0);
    calc_dinv<<<divup(TOTAL, 256), 256>>>(c.i + I_RP + 4 * RPSZ, c.f + O_DINV, TOTAL);
    run_cheb(c, 4, E, cheb_W, cheb_b, lamp, H);
    run_cheb(c, 4, H, cheb_W, cheb_b, lamp, CH2);
    run_gat(c, 4, 4, CH2, TOTAL, PRED, gat_Wl, gat_bl, gat_Wr, gat_br, gat_at, USE);

    // ---- mlp1 / mlp2 ----
    run_mlp(c, 1, UIM, E, mlp_W, mlp_b, mlp_g, mlp_be, HUP);
    run_mlp(c, 2, USE, E, mlp_W, mlp_b, mlp_g, mlp_be, HUS);

    // ---- outputs ----
    hm_soft<<<divup(PRED * 32, 256), 256>>>(HUP, HUS, SP);
    run_mlp(c, 3, SP, HUP, mlp_W, mlp_b, mlp_g, mlp_be, out);

    hm_soft<<<divup(PRED * 32, 256), 256>>>(HUS, HUP, SP);
    run_mlp(c, 4, SP, HUS, mlp_W, mlp_b, mlp_g, mlp_be, out + S_PRED);
}